// round 14
// baseline (speedup 1.0000x reference)
#include <cuda_runtime.h>
#include <cuda_fp16.h>
#include <math.h>
#include <cstdint>

// Problem dims (fixed for this dataset entry)
#define Bb 4
#define Ss 4096
#define Dd 1024
#define Nn 256
#define Mm (Bb*Ss)            // 16384 tokens
#define CHUNK 64
#define NCHUNK (Ss/CHUNK)     // 64

// Scratch (allocations forbidden -> device globals)
__device__ __half g_xh[(size_t)Mm*Dd];      // 32 MB  x (fp16)
__device__ __half g_th[(size_t)Mm*Nn];      // 8 MB   states (fp16)
__device__ float  g_u[(size_t)Mm*Nn];       // 16 MB  input projection
__device__ __half g_wi0[Nn*Dd];             // W_in  (fp16)
__device__ __half g_wo0[Dd*Nn];             // W_out (fp16)
__device__ __half g_ws0[Dd*Dd];             // W_skip (fp16)
__device__ float  g_loc[Bb*NCHUNK*Nn];
__device__ float  g_init[Bb*NCHUNK*Nn];
__device__ float  g_decay[Nn];
__device__ float  g_decayL[Nn];

// ---------------------------------------------------------------------------
__global__ void k_decay(const float* __restrict__ log_decay) {
    int n = threadIdx.x;
    float d = 1.0f / (1.0f + expf(-log_decay[n]));
    g_decay[n] = d;
    float p = d;
    #pragma unroll
    for (int i = 0; i < 6; i++) p *= p;
    g_decayL[n] = p;
}

// Convert fp32 -> fp16 (vectorized: 4 floats per thread)
__global__ void k_cvtW(const float* __restrict__ src, __half* __restrict__ d0, int n4) {
    int i = blockIdx.x * blockDim.x + threadIdx.x;
    if (i < n4) {
        float4 v = ((const float4*)src)[i];
        __half2* o = (__half2*)d0;
        o[2*i]   = __floats2half2_rn(v.x, v.y);
        o[2*i+1] = __floats2half2_rn(v.z, v.w);
    }
}

// ---------------------------------------------------------------------------
// RMSNorm: one block per token, 256 threads; emits fp16 x
__global__ void __launch_bounds__(256) k_rmsnorm(const float* __restrict__ tokens,
                                                 const float* __restrict__ norm_w) {
    int t = blockIdx.x;
    const float4* tp = (const float4*)(tokens + (size_t)t * Dd);
    float4 v = tp[threadIdx.x];
    float ss = v.x*v.x + v.y*v.y + v.z*v.z + v.w*v.w;
    #pragma unroll
    for (int o = 16; o > 0; o >>= 1) ss += __shfl_xor_sync(0xffffffffu, ss, o);
    __shared__ float wsum[8];
    int wid = threadIdx.x >> 5, lane = threadIdx.x & 31;
    if (lane == 0) wsum[wid] = ss;
    __syncthreads();
    float tot = 0.f;
    #pragma unroll
    for (int i = 0; i < 8; i++) tot += wsum[i];
    float scale = rsqrtf(tot * (1.0f / Dd) + 1e-4f);
    float4 w = ((const float4*)norm_w)[threadIdx.x];
    __half2* ph = (__half2*)(g_xh + (size_t)t * Dd);
    ph[2*threadIdx.x]   = __floats2half2_rn(v.x * scale * w.x, v.y * scale * w.y);
    ph[2*threadIdx.x+1] = __floats2half2_rn(v.z * scale * w.z, v.w * scale * w.w);
}

// ---------------------------------------------------------------------------
// fp16 tensor-core GEMM, 256 threads, 256x128 tile, cp.async 4-stage, BK=32.
// C[m,n] = sum_k A[m,k]*B[n,k] (+bias0[n]) (+bias1[n]) (+src[m,n])
// Fused second product (A2,B2,K2) continues the same k-tile pipeline.
// 8 warps (4m x 2n), warp tile 64x64 (per-warp code identical to prev round
// -> bit-identical accumulation). Subtile layout: rows x 32B, 16B-chunk
// swizzle phys_chunk = chunk ^ ((row>>2)&1); conflict-free cp.async + LDSM.
// A subtile 256x32B = 8KB, B subtile 128x32B = 4KB; stage = 2 subtiles.

__device__ __forceinline__ void mma_f16(float* d, const uint32_t* a, const uint32_t* b) {
    asm volatile(
        "mma.sync.aligned.m16n8k16.row.col.f32.f16.f16.f32 "
        "{%0,%1,%2,%3},{%4,%5,%6,%7},{%8,%9},{%0,%1,%2,%3};"
        : "+f"(d[0]), "+f"(d[1]), "+f"(d[2]), "+f"(d[3])
        : "r"(a[0]), "r"(a[1]), "r"(a[2]), "r"(a[3]),
          "r"(b[0]), "r"(b[1]));
}

__device__ __forceinline__ void ldsm4(uint32_t* r, uint32_t addr) {
    asm volatile("ldmatrix.sync.aligned.m8n8.x4.shared.b16 {%0,%1,%2,%3}, [%4];"
        : "=r"(r[0]), "=r"(r[1]), "=r"(r[2]), "=r"(r[3]) : "r"(addr));
}

__device__ __forceinline__ void cp16(uint32_t saddr, const void* gaddr) {
    asm volatile("cp.async.cg.shared.global [%0], [%1], 16;" :: "r"(saddr), "l"(gaddr));
}
#define CP_COMMIT() asm volatile("cp.async.commit_group;" ::: "memory")
#define CP_WAIT2()  asm volatile("cp.async.wait_group 2;" ::: "memory")

__device__ __forceinline__ int swz_off(int row, int chunk) {
    return row * 32 + ((chunk ^ ((row >> 2) & 1)) * 16);
}

#define NSTAGE 4
#define A_STAGEB 16384   // 2 subtiles x 8KB
#define B_STAGEB 8192    // 2 subtiles x 4KB
#define GEMM_SMEM (NSTAGE * (A_STAGEB + B_STAGEB))   // 96 KB

__global__ void __launch_bounds__(256) k_gemmh(
    const __half* __restrict__ A1, const __half* __restrict__ B1, int K1,
    const __half* __restrict__ A2, const __half* __restrict__ B2, int K2,
    float* __restrict__ C, const float* __restrict__ src,
    const float* __restrict__ bias0, const float* __restrict__ bias1,
    int M, int N)
{
    extern __shared__ __align__(16) uint8_t dsm[];
    const uint32_t uA = (uint32_t)__cvta_generic_to_shared(dsm);
    const uint32_t uB = uA + NSTAGE * A_STAGEB;

    const int tid = threadIdx.x;
    const int lane = tid & 31;
    const int w = tid >> 5;               // 0..7
    const int wm0 = (w >> 1) * 64;        // 0,64,128,192
    const int wn0 = (w & 1) * 64;         // 0,64
    const int m0 = blockIdx.y * 256;
    const int n0 = blockIdx.x * 128;

    // ldmatrix per-lane offsets (within one subtile).
    int offA[4], offB[4];
    {
        int r8 = lane & 7;
        int msel = (lane >> 3) & 1;   // A: +8 rows for mats 1,3
        int csel = (lane >> 4) & 1;   // A: chunk 1 for mats 2,3
        #pragma unroll
        for (int mt = 0; mt < 4; mt++)
            offA[mt] = swz_off(wm0 + mt * 16 + r8 + msel * 8, csel);
        int nsel = (lane >> 4) & 1;   // B: +8 rows for mats 2,3
        int bcsel = (lane >> 3) & 1;  // B: chunk 1 for mats 1,3
        #pragma unroll
        for (int ntp = 0; ntp < 4; ntp++)
            offB[ntp] = swz_off(wn0 + ntp * 16 + r8 + nsel * 8, bcsel);
    }
    // loader offsets
    const int stsA0 = swz_off(tid, 0);            // A: row tid (0..255)
    const int stsA1 = swz_off(tid, 1);
    const int brow  = tid & 127;                   // B: row, 2 threads/row
    const int bchk  = tid >> 7;                    // B: chunk 0/1
    const int stsB  = swz_off(brow, bchk);

    const __half* A1p = A1 + (size_t)(m0 + tid) * K1;
    const __half* B1p = B1 + (size_t)(n0 + brow) * K1;
    const __half* A2p = A2 ? A2 + (size_t)(m0 + tid) * K2 : nullptr;
    const __half* B2p = A2 ? B2 + (size_t)(n0 + brow) * K2 : nullptr;

    const int t1 = K1 / 32;
    const int T = t1 + (A2 ? K2 / 32 : 0);

    auto issue = [&](int i) {
        const int slot = i & (NSTAGE - 1);
        const uint32_t dA = uA + slot * A_STAGEB;
        const uint32_t dB = uB + slot * B_STAGEB;
        const __half *ap, *bp; int k0;
        if (i < t1) { ap = A1p; bp = B1p; k0 = i * 32; }
        else        { ap = A2p; bp = B2p; k0 = (i - t1) * 32; }
        #pragma unroll
        for (int s = 0; s < 2; s++) {
            cp16(dA + s * 8192 + stsA0, ap + k0 + s * 16);
            cp16(dA + s * 8192 + stsA1, ap + k0 + s * 16 + 8);
            cp16(dB + s * 4096 + stsB,  bp + k0 + s * 16 + bchk * 8);
        }
        CP_COMMIT();
    };

    float acc[4][8][4];
    #pragma unroll
    for (int mt = 0; mt < 4; mt++)
        #pragma unroll
        for (int nt = 0; nt < 8; nt++)
            #pragma unroll
            for (int r = 0; r < 4; r++) acc[mt][nt][r] = 0.f;

    issue(0); issue(1); issue(2);

    for (int i = 0; i < T; i++) {
        CP_WAIT2();          // newest 2 groups are for tiles > i -> tile i resident
        __syncthreads();     // all warps done with slot (i+3)%4's previous contents
        if (i + 3 < T) issue(i + 3);
        else           CP_COMMIT();   // keep group bookkeeping aligned (empty group)

        const int slot = i & (NSTAGE - 1);
        #pragma unroll
        for (int s = 0; s < 2; s++) {
            const uint32_t aA = uA + slot * A_STAGEB + s * 8192;
            const uint32_t aB = uB + slot * B_STAGEB + s * 4096;
            uint32_t bfr[4][4];
            #pragma unroll
            for (int ntp = 0; ntp < 4; ntp++)
                ldsm4(bfr[ntp], aB + offB[ntp]);
            #pragma unroll
            for (int mt = 0; mt < 4; mt++) {
                uint32_t afr[4];
                ldsm4(afr, aA + offA[mt]);
                #pragma unroll
                for (int nt = 0; nt < 8; nt++)
                    mma_f16(acc[mt][nt], afr, &bfr[nt >> 1][(nt & 1) * 2]);
            }
        }
    }

    // epilogue
    const int g = lane >> 2;
    const int t4 = lane & 3;

    #pragma unroll
    for (int nt = 0; nt < 8; nt++) {
        int c = n0 + wn0 + nt * 8 + 2 * t4;
        float add0 = 0.f, add1 = 0.f;
        if (bias0) { add0 += bias0[c]; add1 += bias0[c + 1]; }
        if (bias1) { add0 += bias1[c]; add1 += bias1[c + 1]; }
        #pragma unroll
        for (int mt = 0; mt < 4; mt++) {
            int r0 = m0 + wm0 + mt * 16 + g;
            int r1 = r0 + 8;
            float2 v0 = make_float2(acc[mt][nt][0] + add0, acc[mt][nt][1] + add1);
            float2 v1 = make_float2(acc[mt][nt][2] + add0, acc[mt][nt][3] + add1);
            size_t o0 = (size_t)r0 * N + c;
            size_t o1 = (size_t)r1 * N + c;
            if (src) {
                float2 s0 = *(const float2*)(src + o0);
                float2 s1 = *(const float2*)(src + o1);
                v0.x += s0.x; v0.y += s0.y;
                v1.x += s1.x; v1.y += s1.y;
            }
            *(float2*)(C + o0) = v0;
            *(float2*)(C + o1) = v1;
        }
    }
}

// ---------------------------------------------------------------------------
// Chunked linear scan: state_t = decay*state_{t-1} + u_t
__global__ void __launch_bounds__(256) k_scan1() {
    int c = blockIdx.x, b = blockIdx.y, n = threadIdx.x;
    float d = g_decay[n];
    const float* up = g_u + ((size_t)(b*Ss + c*CHUNK)) * Nn + n;
    float s = 0.f;
    #pragma unroll 8
    for (int t = 0; t < CHUNK; t++) s = fmaf(d, s, up[(size_t)t * Nn]);
    g_loc[(b*NCHUNK + c)*Nn + n] = s;
}

__global__ void k_scan2() {
    int idx = threadIdx.x + blockIdx.x * blockDim.x;   // <<<4,256>>> -> 1024
    int b = idx >> 8, n = idx & 255;
    float dL = g_decayL[n];
    float init = 0.f;
    for (int c = 0; c < NCHUNK; c++) {
        g_init[(b*NCHUNK + c)*Nn + n] = init;
        init = fmaf(dL, init, g_loc[(b*NCHUNK + c)*Nn + n]);
    }
}

// Pass 3: rescan with correct init, write fp16 states
__global__ void __launch_bounds__(256) k_scan3() {
    int c = blockIdx.x, b = blockIdx.y, n = threadIdx.x;
    float d = g_decay[n];
    size_t base = ((size_t)(b*Ss + c*CHUNK)) * Nn + n;
    float s = g_init[(b*NCHUNK + c)*Nn + n];
    #pragma unroll 4
    for (int t = 0; t < CHUNK; t++) {
        s = fmaf(d, s, g_u[base + (size_t)t * Nn]);
        g_th[base + (size_t)t * Nn] = __float2half_rn(s);
    }
}

// ---------------------------------------------------------------------------
extern "C" void kernel_launch(void* const* d_in, const int* in_sizes, int n_in,
                              void* d_out, int out_size)
{
    const float* tokens    = (const float*)d_in[0];
    const float* norm_w    = (const float*)d_in[1];
    const float* W_in      = (const float*)d_in[2];
    const float* b_in      = (const float*)d_in[3];
    const float* W_out     = (const float*)d_in[4];
    const float* b_out     = (const float*)d_in[5];
    const float* W_skip    = (const float*)d_in[6];
    const float* b_skip    = (const float*)d_in[7];
    const float* log_decay = (const float*)d_in[8];
    float* out = (float*)d_out;

    void *p;
    cudaGetSymbolAddress(&p, g_xh);  __half* xh = (__half*)p;
    cudaGetSymbolAddress(&p, g_th);  __half* th = (__half*)p;
    cudaGetSymbolAddress(&p, g_u);   float*  u  = (float*)p;
    cudaGetSymbolAddress(&p, g_wi0); __half* wi0 = (__half*)p;
    cudaGetSymbolAddress(&p, g_wo0); __half* wo0 = (__half*)p;
    cudaGetSymbolAddress(&p, g_ws0); __half* ws0 = (__half*)p;

    // allow 96KB dynamic smem (idempotent; host-side, not a stream op)
    cudaFuncSetAttribute(k_gemmh, cudaFuncAttributeMaxDynamicSharedMemorySize, GEMM_SMEM);

    // 1) decay precompute + weight converts
    k_decay<<<1, Nn>>>(log_decay);
    k_cvtW<<<(Nn*Dd/4 + 255)/256, 256>>>(W_in,   wi0, Nn*Dd/4);
    k_cvtW<<<(Dd*Nn/4 + 255)/256, 256>>>(W_out,  wo0, Dd*Nn/4);
    k_cvtW<<<(Dd*Dd/4 + 255)/256, 256>>>(W_skip, ws0, Dd*Dd/4);

    // 2) RMSNorm -> fp16 x
    k_rmsnorm<<<Mm, 256>>>(tokens, norm_w);

    // 3) u = x @ W_in^T + b_in   [16384 x 256], K=1024
    {
        dim3 g(Nn/128, Mm/256);    // (2, 64)
        k_gemmh<<<g, 256, GEMM_SMEM>>>(xh, wi0, Dd,
                                       nullptr, nullptr, 0,
                                       u, nullptr, b_in, nullptr, Mm, Nn);
    }

    // 4-6) chunked scan -> fp16 states
    {
        dim3 g(NCHUNK, Bb);
        k_scan1<<<g, 256>>>();
        k_scan2<<<4, 256>>>();
        k_scan3<<<g, 256>>>();
    }

    // 7) out = states @ W_out^T + x @ W_skip^T + tokens + b_out + b_skip
    {
        dim3 g(Dd/128, Mm/256);    // (8, 64)
        k_gemmh<<<g, 256, GEMM_SMEM>>>(th, wo0, Nn,
                                       xh, ws0, Dd,
                                       out, tokens, b_out, b_skip, Mm, Dd);
    }
}

// round 15
// speedup vs baseline: 1.0323x; 1.0323x over previous
#include <cuda_runtime.h>
#include <cuda_fp16.h>
#include <math.h>
#include <cstdint>

// Problem dims (fixed for this dataset entry)
#define Bb 4
#define Ss 4096
#define Dd 1024
#define Nn 256
#define Mm (Bb*Ss)            // 16384 tokens
#define CHUNK 64
#define NCHUNK (Ss/CHUNK)     // 64

// Scratch (allocations forbidden -> device globals)
__device__ __half g_xh[(size_t)Mm*Dd];      // 32 MB  x (fp16)
__device__ __half g_th[(size_t)Mm*Nn];      // 8 MB   states (fp16)
__device__ float  g_u[(size_t)Mm*Nn];       // 16 MB  input projection
__device__ __half g_wi0[Nn*Dd];             // W_in  (fp16)
__device__ __half g_wo0[Dd*Nn];             // W_out (fp16)
__device__ __half g_ws0[Dd*Dd];             // W_skip (fp16)
__device__ float  g_loc[Bb*NCHUNK*Nn];
__device__ float  g_init[Bb*NCHUNK*Nn];
__device__ float  g_decay[Nn];
__device__ float  g_decayL[Nn];

// ---------------------------------------------------------------------------
__global__ void k_decay(const float* __restrict__ log_decay) {
    int n = threadIdx.x;
    float d = 1.0f / (1.0f + expf(-log_decay[n]));
    g_decay[n] = d;
    float p = d;
    #pragma unroll
    for (int i = 0; i < 6; i++) p *= p;
    g_decayL[n] = p;
}

// Convert all three weight matrices fp32 -> fp16 in one launch.
// Layout: [0, NW1) -> wi0, [NW1, NW1+NW2) -> wo0, rest -> ws0 (float4 units).
#define NW1 (Nn*Dd/4)
#define NW2 (Dd*Nn/4)
#define NW3 (Dd*Dd/4)
__global__ void k_cvtW3(const float* __restrict__ Wi, const float* __restrict__ Wo,
                        const float* __restrict__ Ws) {
    int i = blockIdx.x * blockDim.x + threadIdx.x;
    const float* src; __half* dst; int j;
    if (i < NW1)            { src = Wi; dst = g_wi0; j = i; }
    else if (i < NW1 + NW2) { src = Wo; dst = g_wo0; j = i - NW1; }
    else if (i < NW1 + NW2 + NW3) { src = Ws; dst = g_ws0; j = i - NW1 - NW2; }
    else return;
    float4 v = ((const float4*)src)[j];
    __half2* o = (__half2*)dst;
    o[2*j]   = __floats2half2_rn(v.x, v.y);
    o[2*j+1] = __floats2half2_rn(v.z, v.w);
}

// ---------------------------------------------------------------------------
// RMSNorm: one block per token, 256 threads; emits fp16 x
__global__ void __launch_bounds__(256) k_rmsnorm(const float* __restrict__ tokens,
                                                 const float* __restrict__ norm_w) {
    int t = blockIdx.x;
    const float4* tp = (const float4*)(tokens + (size_t)t * Dd);
    float4 v = tp[threadIdx.x];
    float ss = v.x*v.x + v.y*v.y + v.z*v.z + v.w*v.w;
    #pragma unroll
    for (int o = 16; o > 0; o >>= 1) ss += __shfl_xor_sync(0xffffffffu, ss, o);
    __shared__ float wsum[8];
    int wid = threadIdx.x >> 5, lane = threadIdx.x & 31;
    if (lane == 0) wsum[wid] = ss;
    __syncthreads();
    float tot = 0.f;
    #pragma unroll
    for (int i = 0; i < 8; i++) tot += wsum[i];
    float scale = rsqrtf(tot * (1.0f / Dd) + 1e-4f);
    float4 w = ((const float4*)norm_w)[threadIdx.x];
    __half2* ph = (__half2*)(g_xh + (size_t)t * Dd);
    ph[2*threadIdx.x]   = __floats2half2_rn(v.x * scale * w.x, v.y * scale * w.y);
    ph[2*threadIdx.x+1] = __floats2half2_rn(v.z * scale * w.z, v.w * scale * w.w);
}

// ---------------------------------------------------------------------------
// fp16 tensor-core GEMM, cp.async 3-stage pipeline, BK=64, ldmatrix.
// C[m,n] = sum_k A[m,k]*B[n,k] (+bias0[n]) (+bias1[n]) (+src[m,n])
// Fused second product (A2,B2,K2) continues the same k-tile pipeline.
// CTA: 128x128 tile, 128 threads = 4 warps (2x2), warp tile 64x64.
// Stage = 4 subtiles of the proven layout: 128 rows x 32B, 16B-chunk swizzle
//   phys_chunk = chunk ^ ((row>>2)&1)  -> conflict-free cp.async + LDSM.
// k16 subtiles processed in global k order -> accumulation bit-identical
// to prior rounds (canary rel_err = 3.080643e-4).

__device__ __forceinline__ void mma_f16(float* d, const uint32_t* a, const uint32_t* b) {
    asm volatile(
        "mma.sync.aligned.m16n8k16.row.col.f32.f16.f16.f32 "
        "{%0,%1,%2,%3},{%4,%5,%6,%7},{%8,%9},{%0,%1,%2,%3};"
        : "+f"(d[0]), "+f"(d[1]), "+f"(d[2]), "+f"(d[3])
        : "r"(a[0]), "r"(a[1]), "r"(a[2]), "r"(a[3]),
          "r"(b[0]), "r"(b[1]));
}

__device__ __forceinline__ void ldsm4(uint32_t* r, uint32_t addr) {
    asm volatile("ldmatrix.sync.aligned.m8n8.x4.shared.b16 {%0,%1,%2,%3}, [%4];"
        : "=r"(r[0]), "=r"(r[1]), "=r"(r[2]), "=r"(r[3]) : "r"(addr));
}

__device__ __forceinline__ void cp16(uint32_t saddr, const void* gaddr) {
    asm volatile("cp.async.cg.shared.global [%0], [%1], 16;" :: "r"(saddr), "l"(gaddr));
}
#define CP_COMMIT() asm volatile("cp.async.commit_group;" ::: "memory")
#define CP_WAIT1()  asm volatile("cp.async.wait_group 1;" ::: "memory")

__device__ __forceinline__ int swz_off(int row, int chunk) {
    return row * 32 + ((chunk ^ ((row >> 2) & 1)) * 16);
}

#define NSTAGE 3
#define STAGEB 16384              // per operand per stage: 4 subtiles x 4096B
#define GEMM_SMEM (NSTAGE * 2 * STAGEB)   // 96 KB dynamic

__global__ void __launch_bounds__(128) k_gemmh(
    const __half* __restrict__ A1, const __half* __restrict__ B1, int K1,
    const __half* __restrict__ A2, const __half* __restrict__ B2, int K2,
    float* __restrict__ C, const float* __restrict__ src,
    const float* __restrict__ bias0, const float* __restrict__ bias1,
    int M, int N)
{
    extern __shared__ __align__(16) uint8_t dsm[];
    const uint32_t uA = (uint32_t)__cvta_generic_to_shared(dsm);
    const uint32_t uB = uA + NSTAGE * STAGEB;

    const int tid = threadIdx.x;
    const int lane = tid & 31;
    const int w = tid >> 5;
    const int wm0 = (w >> 1) * 64;
    const int wn0 = (w & 1) * 64;
    const int m0 = blockIdx.y * 128;
    const int n0 = blockIdx.x * 128;

    // ldmatrix per-lane offsets (within one 4KB subtile).
    int offA[4], offB[4];
    {
        int r8 = lane & 7;
        int msel = (lane >> 3) & 1;   // A: +8 rows for mats 1,3
        int csel = (lane >> 4) & 1;   // A: chunk 1 for mats 2,3
        #pragma unroll
        for (int mt = 0; mt < 4; mt++)
            offA[mt] = swz_off(wm0 + mt * 16 + r8 + msel * 8, csel);
        int nsel = (lane >> 4) & 1;   // B: +8 rows for mats 2,3
        int bcsel = (lane >> 3) & 1;  // B: chunk 1 for mats 1,3
        #pragma unroll
        for (int ntp = 0; ntp < 4; ntp++)
            offB[ntp] = swz_off(wn0 + ntp * 16 + r8 + nsel * 8, bcsel);
    }
    const int stsw0 = swz_off(tid, 0);
    const int stsw1 = swz_off(tid, 1);

    const __half* A1p = A1 + (size_t)(m0 + tid) * K1;
    const __half* B1p = B1 + (size_t)(n0 + tid) * K1;
    const __half* A2p = A2 ? A2 + (size_t)(m0 + tid) * K2 : nullptr;
    const __half* B2p = A2 ? B2 + (size_t)(n0 + tid) * K2 : nullptr;

    const int t1 = K1 / 64;
    const int T = t1 + (A2 ? K2 / 64 : 0);

    // issue async loads for BK=64 k-tile i into slot i % NSTAGE
    auto issue = [&](int i) {
        const int slot = i % NSTAGE;
        const uint32_t dA = uA + slot * STAGEB;
        const uint32_t dB = uB + slot * STAGEB;
        const __half *ap, *bp; int k0;
        if (i < t1) { ap = A1p; bp = B1p; k0 = i * 64; }
        else        { ap = A2p; bp = B2p; k0 = (i - t1) * 64; }
        #pragma unroll
        for (int s = 0; s < 4; s++) {
            cp16(dA + s * 4096 + stsw0, ap + k0 + s * 16);
            cp16(dA + s * 4096 + stsw1, ap + k0 + s * 16 + 8);
            cp16(dB + s * 4096 + stsw0, bp + k0 + s * 16);
            cp16(dB + s * 4096 + stsw1, bp + k0 + s * 16 + 8);
        }
        CP_COMMIT();
    };

    float acc[4][8][4];
    #pragma unroll
    for (int mt = 0; mt < 4; mt++)
        #pragma unroll
        for (int nt = 0; nt < 8; nt++)
            #pragma unroll
            for (int r = 0; r < 4; r++) acc[mt][nt][r] = 0.f;

    issue(0);
    issue(1);

    for (int i = 0; i < T; i++) {
        CP_WAIT1();          // all but newest group done -> tile i resident
        __syncthreads();     // all warps past compute(i-1): slot (i+2)%3 free
        if (i + 2 < T) issue(i + 2);
        else           CP_COMMIT();   // empty group keeps wait_group semantics

        const int slot = i % NSTAGE;
        #pragma unroll
        for (int s = 0; s < 4; s++) {
            const uint32_t aA = uA + slot * STAGEB + s * 4096;
            const uint32_t aB = uB + slot * STAGEB + s * 4096;
            uint32_t bfr[4][4];
            #pragma unroll
            for (int ntp = 0; ntp < 4; ntp++)
                ldsm4(bfr[ntp], aB + offB[ntp]);
            #pragma unroll
            for (int mt = 0; mt < 4; mt++) {
                uint32_t afr[4];
                ldsm4(afr, aA + offA[mt]);
                #pragma unroll
                for (int nt = 0; nt < 8; nt++)
                    mma_f16(acc[mt][nt], afr, &bfr[nt >> 1][(nt & 1) * 2]);
            }
        }
    }

    // epilogue
    const int g = lane >> 2;
    const int t4 = lane & 3;

    #pragma unroll
    for (int nt = 0; nt < 8; nt++) {
        int c = n0 + wn0 + nt * 8 + 2 * t4;
        float add0 = 0.f, add1 = 0.f;
        if (bias0) { add0 += bias0[c]; add1 += bias0[c + 1]; }
        if (bias1) { add0 += bias1[c]; add1 += bias1[c + 1]; }
        #pragma unroll
        for (int mt = 0; mt < 4; mt++) {
            int r0 = m0 + wm0 + mt * 16 + g;
            int r1 = r0 + 8;
            float2 v0 = make_float2(acc[mt][nt][0] + add0, acc[mt][nt][1] + add1);
            float2 v1 = make_float2(acc[mt][nt][2] + add0, acc[mt][nt][3] + add1);
            size_t o0 = (size_t)r0 * N + c;
            size_t o1 = (size_t)r1 * N + c;
            if (src) {
                float2 s0 = *(const float2*)(src + o0);
                float2 s1 = *(const float2*)(src + o1);
                v0.x += s0.x; v0.y += s0.y;
                v1.x += s1.x; v1.y += s1.y;
            }
            *(float2*)(C + o0) = v0;
            *(float2*)(C + o1) = v1;
        }
    }
}

// ---------------------------------------------------------------------------
// Chunked linear scan: state_t = decay*state_{t-1} + u_t
__global__ void __launch_bounds__(256) k_scan1() {
    int c = blockIdx.x, b = blockIdx.y, n = threadIdx.x;
    float d = g_decay[n];
    const float* up = g_u + ((size_t)(b*Ss + c*CHUNK)) * Nn + n;
    float s = 0.f;
    #pragma unroll 8
    for (int t = 0; t < CHUNK; t++) s = fmaf(d, s, up[(size_t)t * Nn]);
    g_loc[(b*NCHUNK + c)*Nn + n] = s;
}

__global__ void k_scan2() {
    int idx = threadIdx.x + blockIdx.x * blockDim.x;   // <<<4,256>>> -> 1024
    int b = idx >> 8, n = idx & 255;
    float dL = g_decayL[n];
    float init = 0.f;
    for (int c = 0; c < NCHUNK; c++) {
        g_init[(b*NCHUNK + c)*Nn + n] = init;
        init = fmaf(dL, init, g_loc[(b*NCHUNK + c)*Nn + n]);
    }
}

// Pass 3: rescan with correct init, write fp16 states
__global__ void __launch_bounds__(256) k_scan3() {
    int c = blockIdx.x, b = blockIdx.y, n = threadIdx.x;
    float d = g_decay[n];
    size_t base = ((size_t)(b*Ss + c*CHUNK)) * Nn + n;
    float s = g_init[(b*NCHUNK + c)*Nn + n];
    #pragma unroll 4
    for (int t = 0; t < CHUNK; t++) {
        s = fmaf(d, s, g_u[base + (size_t)t * Nn]);
        g_th[base + (size_t)t * Nn] = __float2half_rn(s);
    }
}

// ---------------------------------------------------------------------------
extern "C" void kernel_launch(void* const* d_in, const int* in_sizes, int n_in,
                              void* d_out, int out_size)
{
    const float* tokens    = (const float*)d_in[0];
    const float* norm_w    = (const float*)d_in[1];
    const float* W_in      = (const float*)d_in[2];
    const float* b_in      = (const float*)d_in[3];
    const float* W_out     = (const float*)d_in[4];
    const float* b_out     = (const float*)d_in[5];
    const float* W_skip    = (const float*)d_in[6];
    const float* b_skip    = (const float*)d_in[7];
    const float* log_decay = (const float*)d_in[8];
    float* out = (float*)d_out;

    void *p;
    cudaGetSymbolAddress(&p, g_xh);  __half* xh = (__half*)p;
    cudaGetSymbolAddress(&p, g_th);  __half* th = (__half*)p;
    cudaGetSymbolAddress(&p, g_u);   float*  u  = (float*)p;
    cudaGetSymbolAddress(&p, g_wi0); __half* wi0 = (__half*)p;
    cudaGetSymbolAddress(&p, g_wo0); __half* wo0 = (__half*)p;
    cudaGetSymbolAddress(&p, g_ws0); __half* ws0 = (__half*)p;

    // allow 96KB dynamic smem (host-side attribute, idempotent)
    cudaFuncSetAttribute(k_gemmh, cudaFuncAttributeMaxDynamicSharedMemorySize, GEMM_SMEM);

    // 1) decay precompute + all weight converts in one launch
    k_decay<<<1, Nn>>>(log_decay);
    k_cvtW3<<<(NW1 + NW2 + NW3 + 255)/256, 256>>>(W_in, W_out, W_skip);

    // 2) RMSNorm -> fp16 x
    k_rmsnorm<<<Mm, 256>>>(tokens, norm_w);

    // 3) u = x @ W_in^T + b_in   [16384 x 256], K=1024
    {
        dim3 g(Nn/128, Mm/128);    // (2, 128)
        k_gemmh<<<g, 128, GEMM_SMEM>>>(xh, wi0, Dd,
                                       nullptr, nullptr, 0,
                                       u, nullptr, b_in, nullptr, Mm, Nn);
    }

    // 4-6) chunked scan -> fp16 states
    {
        dim3 g(NCHUNK, Bb);
        k_scan1<<<g, 256>>>();
        k_scan2<<<4, 256>>>();
        k_scan3<<<g, 256>>>();
    }

    // 7) out = states @ W_out^T + x @ W_skip^T + tokens + b_out + b_skip
    {
        dim3 g(Dd/128, Mm/128);    // (8, 128)
        k_gemmh<<<g, 128, GEMM_SMEM>>>(th, wo0, Nn,
                                       xh, ws0, Dd,
                                       out, tokens, b_out, b_skip, Mm, Dd);
    }
}

// round 17
// speedup vs baseline: 1.0815x; 1.0476x over previous
#include <cuda_runtime.h>
#include <cuda_fp16.h>
#include <math.h>
#include <cstdint>

// Problem dims (fixed for this dataset entry)
#define Bb 4
#define Ss 4096
#define Dd 1024
#define Nn 256
#define Mm (Bb*Ss)            // 16384 tokens
#define CHUNK 64
#define NCHUNK (Ss/CHUNK)     // 64

// Scratch (allocations forbidden -> device globals)
__device__ __half g_xh[(size_t)Mm*Dd];      // 32 MB  x (fp16)
__device__ __half g_th[(size_t)Mm*Nn];      // 8 MB   states (fp16)
__device__ float  g_u[(size_t)Mm*Nn];       // 16 MB  input projection
__device__ __half g_wi0[Nn*Dd];             // W_in  (fp16)
__device__ __half g_wo0[Dd*Nn];             // W_out (fp16)
__device__ __half g_ws0[Dd*Dd];             // W_skip (fp16)
__device__ float  g_loc[Bb*NCHUNK*Nn];
__device__ float  g_init[Bb*NCHUNK*Nn];
__device__ float  g_decay[Nn];
__device__ float  g_decayL[Nn];

// ---------------------------------------------------------------------------
__global__ void k_decay(const float* __restrict__ log_decay) {
    int n = threadIdx.x;
    float d = 1.0f / (1.0f + expf(-log_decay[n]));
    g_decay[n] = d;
    float p = d;
    #pragma unroll
    for (int i = 0; i < 6; i++) p *= p;
    g_decayL[n] = p;
}

// Convert all three weight matrices fp32 -> fp16 in one launch.
#define NW1 (Nn*Dd/4)
#define NW2 (Dd*Nn/4)
#define NW3 (Dd*Dd/4)
__global__ void k_cvtW3(const float* __restrict__ Wi, const float* __restrict__ Wo,
                        const float* __restrict__ Ws) {
    int i = blockIdx.x * blockDim.x + threadIdx.x;
    const float* src; __half* dst; int j;
    if (i < NW1)            { src = Wi; dst = g_wi0; j = i; }
    else if (i < NW1 + NW2) { src = Wo; dst = g_wo0; j = i - NW1; }
    else if (i < NW1 + NW2 + NW3) { src = Ws; dst = g_ws0; j = i - NW1 - NW2; }
    else return;
    float4 v = ((const float4*)src)[j];
    __half2* o = (__half2*)dst;
    o[2*j]   = __floats2half2_rn(v.x, v.y);
    o[2*j+1] = __floats2half2_rn(v.z, v.w);
}

// ---------------------------------------------------------------------------
// RMSNorm: one block per token, 256 threads; emits fp16 x
__global__ void __launch_bounds__(256) k_rmsnorm(const float* __restrict__ tokens,
                                                 const float* __restrict__ norm_w) {
    int t = blockIdx.x;
    const float4* tp = (const float4*)(tokens + (size_t)t * Dd);
    float4 v = tp[threadIdx.x];
    float ss = v.x*v.x + v.y*v.y + v.z*v.z + v.w*v.w;
    #pragma unroll
    for (int o = 16; o > 0; o >>= 1) ss += __shfl_xor_sync(0xffffffffu, ss, o);
    __shared__ float wsum[8];
    int wid = threadIdx.x >> 5, lane = threadIdx.x & 31;
    if (lane == 0) wsum[wid] = ss;
    __syncthreads();
    float tot = 0.f;
    #pragma unroll
    for (int i = 0; i < 8; i++) tot += wsum[i];
    float scale = rsqrtf(tot * (1.0f / Dd) + 1e-4f);
    float4 w = ((const float4*)norm_w)[threadIdx.x];
    __half2* ph = (__half2*)(g_xh + (size_t)t * Dd);
    ph[2*threadIdx.x]   = __floats2half2_rn(v.x * scale * w.x, v.y * scale * w.y);
    ph[2*threadIdx.x+1] = __floats2half2_rn(v.z * scale * w.z, v.w * scale * w.w);
}

// ---------------------------------------------------------------------------
// fp16 tensor-core GEMM, 256 threads / 8 warps, 128x128 tile, warp tile 64x32.
// cp.async 4-stage pipeline, BK=32, ldmatrix.
// C[m,n] = sum_k A[m,k]*B[n,k] (+bias0[n]) (+bias1[n]) (+src[m,n])
// Fused second product (A2,B2,K2) continues the same k-tile pipeline.
// Subtile layout (proven): 128 rows x 32B, phys_chunk = chunk ^ ((row>>2)&1).
// Per-output k-order identical to prior rounds -> canary rel_err 3.080643e-4.

__device__ __forceinline__ void mma_f16(float* d, const uint32_t* a, const uint32_t* b) {
    asm volatile(
        "mma.sync.aligned.m16n8k16.row.col.f32.f16.f16.f32 "
        "{%0,%1,%2,%3},{%4,%5,%6,%7},{%8,%9},{%0,%1,%2,%3};"
        : "+f"(d[0]), "+f"(d[1]), "+f"(d[2]), "+f"(d[3])
        : "r"(a[0]), "r"(a[1]), "r"(a[2]), "r"(a[3]),
          "r"(b[0]), "r"(b[1]));
}

__device__ __forceinline__ void ldsm4(uint32_t* r, uint32_t addr) {
    asm volatile("ldmatrix.sync.aligned.m8n8.x4.shared.b16 {%0,%1,%2,%3}, [%4];"
        : "=r"(r[0]), "=r"(r[1]), "=r"(r[2]), "=r"(r[3]) : "r"(addr));
}

__device__ __forceinline__ void cp16(uint32_t saddr, const void* gaddr) {
    asm volatile("cp.async.cg.shared.global [%0], [%1], 16;" :: "r"(saddr), "l"(gaddr));
}
#define CP_COMMIT() asm volatile("cp.async.commit_group;" ::: "memory")
#define CP_WAIT2()  asm volatile("cp.async.wait_group 2;" ::: "memory")

__device__ __forceinline__ int swz_off(int row, int chunk) {
    return row * 32 + ((chunk ^ ((row >> 2) & 1)) * 16);
}

#define NSTAGE 4
#define STAGEB 8192                       // per operand per stage: 2 subtiles x 4KB
#define GEMM_SMEM (NSTAGE * 2 * STAGEB)   // 64 KB dynamic

__global__ void __launch_bounds__(256) k_gemmh(
    const __half* __restrict__ A1, const __half* __restrict__ B1, int K1,
    const __half* __restrict__ A2, const __half* __restrict__ B2, int K2,
    float* __restrict__ C, const float* __restrict__ src,
    const float* __restrict__ bias0, const float* __restrict__ bias1,
    int M, int N)
{
    extern __shared__ __align__(16) uint8_t dsm[];
    const uint32_t uA = (uint32_t)__cvta_generic_to_shared(dsm);
    const uint32_t uB = uA + NSTAGE * STAGEB;

    const int tid = threadIdx.x;
    const int lane = tid & 31;
    const int w = tid >> 5;               // 0..7
    const int wm0 = (w >> 2) * 64;        // 0,64
    const int wn0 = (w & 3) * 32;         // 0,32,64,96
    const int m0 = blockIdx.y * 128;
    const int n0 = blockIdx.x * 128;

    // ldmatrix per-lane offsets (within one 4KB subtile).
    int offA[4], offB[2];
    {
        int r8 = lane & 7;
        int msel = (lane >> 3) & 1;   // A: +8 rows for mats 1,3
        int csel = (lane >> 4) & 1;   // A: chunk 1 for mats 2,3
        #pragma unroll
        for (int mt = 0; mt < 4; mt++)
            offA[mt] = swz_off(wm0 + mt * 16 + r8 + msel * 8, csel);
        int nsel = (lane >> 4) & 1;   // B: +8 rows for mats 2,3
        int bcsel = (lane >> 3) & 1;  // B: chunk 1 for mats 1,3
        #pragma unroll
        for (int ntp = 0; ntp < 2; ntp++)
            offB[ntp] = swz_off(wn0 + ntp * 16 + r8 + nsel * 8, bcsel);
    }
    // loader: 256 threads, 2 threads per row (one per 16B chunk)
    const int lrow = tid & 127;
    const int lchk = tid >> 7;
    const int stsw = swz_off(lrow, lchk);

    const __half* A1p = A1 + (size_t)(m0 + lrow) * K1 + lchk * 8;
    const __half* B1p = B1 + (size_t)(n0 + lrow) * K1 + lchk * 8;
    const __half* A2p = A2 ? A2 + (size_t)(m0 + lrow) * K2 + lchk * 8 : nullptr;
    const __half* B2p = A2 ? B2 + (size_t)(n0 + lrow) * K2 + lchk * 8 : nullptr;

    const int t1 = K1 / 32;
    const int T = t1 + (A2 ? K2 / 32 : 0);

    auto issue = [&](int i) {
        const int slot = i & (NSTAGE - 1);
        const uint32_t dA = uA + slot * STAGEB;
        const uint32_t dB = uB + slot * STAGEB;
        const __half *ap, *bp; int k0;
        if (i < t1) { ap = A1p; bp = B1p; k0 = i * 32; }
        else        { ap = A2p; bp = B2p; k0 = (i - t1) * 32; }
        #pragma unroll
        for (int s = 0; s < 2; s++) {
            cp16(dA + s * 4096 + stsw, ap + k0 + s * 16);
            cp16(dB + s * 4096 + stsw, bp + k0 + s * 16);
        }
        CP_COMMIT();
    };

    float acc[4][4][4];
    #pragma unroll
    for (int mt = 0; mt < 4; mt++)
        #pragma unroll
        for (int nt = 0; nt < 4; nt++)
            #pragma unroll
            for (int r = 0; r < 4; r++) acc[mt][nt][r] = 0.f;

    issue(0); issue(1); issue(2);

    for (int i = 0; i < T; i++) {
        CP_WAIT2();          // newest 2 groups pending at most -> tile i resident
        __syncthreads();     // all warps done computing tile i-1: its slot is free
        if (i + 3 < T) issue(i + 3);
        else           CP_COMMIT();   // empty group keeps wait_group bookkeeping

        const int slot = i & (NSTAGE - 1);
        #pragma unroll
        for (int s = 0; s < 2; s++) {
            const uint32_t aA = uA + slot * STAGEB + s * 4096;
            const uint32_t aB = uB + slot * STAGEB + s * 4096;
            uint32_t bfr[2][4];
            #pragma unroll
            for (int ntp = 0; ntp < 2; ntp++)
                ldsm4(bfr[ntp], aB + offB[ntp]);
            #pragma unroll
            for (int mt = 0; mt < 4; mt++) {
                uint32_t afr[4];
                ldsm4(afr, aA + offA[mt]);
                #pragma unroll
                for (int nt = 0; nt < 4; nt++)
                    mma_f16(acc[mt][nt], afr, &bfr[nt >> 1][(nt & 1) * 2]);
            }
        }
    }

    // epilogue
    const int g = lane >> 2;
    const int t4 = lane & 3;

    #pragma unroll
    for (int nt = 0; nt < 4; nt++) {
        int c = n0 + wn0 + nt * 8 + 2 * t4;
        float add0 = 0.f, add1 = 0.f;
        if (bias0) { add0 += bias0[c]; add1 += bias0[c + 1]; }
        if (bias1) { add0 += bias1[c]; add1 += bias1[c + 1]; }
        #pragma unroll
        for (int mt = 0; mt < 4; mt++) {
            int r0 = m0 + wm0 + mt * 16 + g;
            int r1 = r0 + 8;
            float2 v0 = make_float2(acc[mt][nt][0] + add0, acc[mt][nt][1] + add1);
            float2 v1 = make_float2(acc[mt][nt][2] + add0, acc[mt][nt][3] + add1);
            size_t o0 = (size_t)r0 * N + c;
            size_t o1 = (size_t)r1 * N + c;
            if (src) {
                float2 s0 = *(const float2*)(src + o0);
                float2 s1 = *(const float2*)(src + o1);
                v0.x += s0.x; v0.y += s0.y;
                v1.x += s1.x; v1.y += s1.y;
            }
            *(float2*)(C + o0) = v0;
            *(float2*)(C + o1) = v1;
        }
    }
}

// ---------------------------------------------------------------------------
// Chunked linear scan: state_t = decay*state_{t-1} + u_t
__global__ void __launch_bounds__(256) k_scan1() {
    int c = blockIdx.x, b = blockIdx.y, n = threadIdx.x;
    float d = g_decay[n];
    const float* up = g_u + ((size_t)(b*Ss + c*CHUNK)) * Nn + n;
    float s = 0.f;
    #pragma unroll 8
    for (int t = 0; t < CHUNK; t++) s = fmaf(d, s, up[(size_t)t * Nn]);
    g_loc[(b*NCHUNK + c)*Nn + n] = s;
}

__global__ void k_scan2() {
    int idx = threadIdx.x + blockIdx.x * blockDim.x;   // <<<4,256>>> -> 1024
    int b = idx >> 8, n = idx & 255;
    float dL = g_decayL[n];
    float init = 0.f;
    for (int c = 0; c < NCHUNK; c++) {
        g_init[(b*NCHUNK + c)*Nn + n] = init;
        init = fmaf(dL, init, g_loc[(b*NCHUNK + c)*Nn + n]);
    }
}

// Pass 3: rescan with correct init, write fp16 states
__global__ void __launch_bounds__(256) k_scan3() {
    int c = blockIdx.x, b = blockIdx.y, n = threadIdx.x;
    float d = g_decay[n];
    size_t base = ((size_t)(b*Ss + c*CHUNK)) * Nn + n;
    float s = g_init[(b*NCHUNK + c)*Nn + n];
    #pragma unroll 4
    for (int t = 0; t < CHUNK; t++) {
        s = fmaf(d, s, g_u[base + (size_t)t * Nn]);
        g_th[base + (size_t)t * Nn] = __float2half_rn(s);
    }
}

// ---------------------------------------------------------------------------
extern "C" void kernel_launch(void* const* d_in, const int* in_sizes, int n_in,
                              void* d_out, int out_size)
{
    const float* tokens    = (const float*)d_in[0];
    const float* norm_w    = (const float*)d_in[1];
    const float* W_in      = (const float*)d_in[2];
    const float* b_in      = (const float*)d_in[3];
    const float* W_out     = (const float*)d_in[4];
    const float* b_out     = (const float*)d_in[5];
    const float* W_skip    = (const float*)d_in[6];
    const float* b_skip    = (const float*)d_in[7];
    const float* log_decay = (const float*)d_in[8];
    float* out = (float*)d_out;

    void *p;
    cudaGetSymbolAddress(&p, g_xh);  __half* xh = (__half*)p;
    cudaGetSymbolAddress(&p, g_th);  __half* th = (__half*)p;
    cudaGetSymbolAddress(&p, g_u);   float*  u  = (float*)p;
    cudaGetSymbolAddress(&p, g_wi0); __half* wi0 = (__half*)p;
    cudaGetSymbolAddress(&p, g_wo0); __half* wo0 = (__half*)p;
    cudaGetSymbolAddress(&p, g_ws0); __half* ws0 = (__half*)p;

    // allow 64KB dynamic smem (host-side attribute, idempotent)
    cudaFuncSetAttribute(k_gemmh, cudaFuncAttributeMaxDynamicSharedMemorySize, GEMM_SMEM);

    // 1) decay precompute + all weight converts in one launch
    k_decay<<<1, Nn>>>(log_decay);
    k_cvtW3<<<(NW1 + NW2 + NW3 + 255)/256, 256>>>(W_in, W_out, W_skip);

    // 2) RMSNorm -> fp16 x
    k_rmsnorm<<<Mm, 256>>>(tokens, norm_w);

    // 3) u = x @ W_in^T + b_in   [16384 x 256], K=1024
    {
        dim3 g(Nn/128, Mm/128);    // (2, 128)
        k_gemmh<<<g, 256, GEMM_SMEM>>>(xh, wi0, Dd,
                                       nullptr, nullptr, 0,
                                       u, nullptr, b_in, nullptr, Mm, Nn);
    }

    // 4-6) chunked scan -> fp16 states
    {
        dim3 g(NCHUNK, Bb);
        k_scan1<<<g, 256>>>();
        k_scan2<<<4, 256>>>();
        k_scan3<<<g, 256>>>();
    }

    // 7) out = states @ W_out^T + x @ W_skip^T + tokens + b_out + b_skip
    {
        dim3 g(Dd/128, Mm/128);    // (8, 128)
        k_gemmh<<<g, 256, GEMM_SMEM>>>(th, wo0, Nn,
                                       xh, ws0, Dd,
                                       out, tokens, b_out, b_skip, Mm, Dd);
    }
}